// round 17
// baseline (speedup 1.0000x reference)
#include <cuda_runtime.h>
#include <cstdint>

// Problem constants
constexpr int B = 8;
constexpr int S = 4096;
constexpr int D = 2048;
constexpr int E = 64;

// Streaming tiling — EXACT R2 shape (measured fastest): grid 2048, multi-wave
constexpr int SCHUNKS = 128;            // partial-sum chunks over S
constexpr int SPC     = S / SCHUNKS;    // 32 rows per chunk
constexpr int DTILES  = 2;              // 2048 d -> 2 tiles of 1024 (256 thr * float4)
constexpr int THR     = 256;
constexpr int GRID    = SCHUNKS * B * DTILES;   // 2048 blocks

// Tail roles: STATIC by bid (bids 0..95 are wave-1, spread <=1 per SM by the
// classic bid->smid LUT). No atomic on any block's exit path.
constexpr int FOLD_BLOCKS   = 32;       // bids [0,32): fold role
constexpr int EXPERT_BLOCKS = E;        // bids [32,96): expert role

// Static scratch (allocation-free rule)
__device__ float g_partial[(size_t)SCHUNKS * B * D];  // 8 MB (fits L2)
__device__ float g_mean[B * D];                       // 64 KB
__device__ float g_logits[B * E];                     // 2 KB
__device__ int   g_c0;   // streaming arrivals (zero-init; reset at end of run)
__device__ int   g_c1;   // fold arrivals
__device__ int   g_c2;   // gemv ticket

// ---------------------------------------------------------------------------
// ONE kernel, grid=2048 multi-wave (HW scheduler load-balances streaming).
//  Phase 1 (all blocks): stream a 32-row x 1024-col chunk -> g_partial,
//    identical to the fastest measured streaming kernel. Exit is
//    fire-and-forget: fence + discarded-return atomicAdd (REDG) + return,
//    so block retirement is never atomic-serialized and waves backfill.
//  Fold role (bids 0..31): park on g_c0==2048 (nanosleep; frees issue slots
//    while later waves stream), then fold 128 partials per position ->
//    g_mean in fixed ascending order. Count on g_c1.
//  Expert role (bids 32..95, e=bid-32): prefetch W[e] into smem right after
//    phase 1 (DRAM read hidden under remaining streaming), park on g_c1==32,
//    warp b computes dot(mean[b], W[e]) -> logits. Ticket on g_c2; the last
//    ticket does top-2 (strict > = lowest-index tie-break, matching
//    jax.lax.top_k) + 2-way softmax and resets counters for graph replays.
// Static roles + fixed-order reductions -> bit-deterministic.
// Output: out[0..15] = weights[B][2], out[16..31] = (float)indices[B][2].
// ---------------------------------------------------------------------------
__global__ __launch_bounds__(THR) void fused_kernel(const float* __restrict__ x,
                                                    const float* __restrict__ W,
                                                    const float* __restrict__ bias,
                                                    float* __restrict__ out) {
    int bid = blockIdx.x;
    int tid = threadIdx.x;

    __shared__ float4 wsm[D / 4];          // 8 KB (expert role)
    __shared__ float  s_logits[B * E];     // 2 KB (final block)
    __shared__ int    s_ticket;

    // ---------------- Phase 1: streaming partial sums (R2-identical) ----------------
    {
        int chunk = bid / (B * DTILES);
        int rem   = bid % (B * DTILES);
        int b     = rem / DTILES;
        int dt    = rem % DTILES;
        int d     = dt * (THR * 4) + tid * 4;

        const float4* __restrict__ xp =
            (const float4*)(x + ((size_t)b * S + (size_t)chunk * SPC) * D + d);
        float4 acc = make_float4(0.f, 0.f, 0.f, 0.f);
#pragma unroll 8
        for (int s = 0; s < SPC; s++) {
            float4 v = xp[(size_t)s * (D / 4)];
            acc.x += v.x; acc.y += v.y; acc.z += v.z; acc.w += v.w;
        }
        *(float4*)(g_partial + (size_t)chunk * (B * D) + (size_t)b * D + d) = acc;
    }
    __syncthreads();

    if (bid >= FOLD_BLOCKS + EXPERT_BLOCKS) {
        // Fire-and-forget exit: discarded atomicAdd lowers to REDG (no return),
        // block retires immediately -> next wave launches without delay.
        if (tid == 0) {
            __threadfence();                // release partial writes
            atomicAdd(&g_c0, 1);
        }
        return;
    }
    if (tid == 0) {
        __threadfence();                    // release this block's partial
        atomicAdd(&g_c0, 1);
    }

    if (bid < FOLD_BLOCKS) {
        // ---------------- Fold role ----------------
        if (tid == 0) {
            while (*(volatile int*)&g_c0 != GRID) __nanosleep(64);  // park
            __threadfence();                // acquire all partials
        }
        __syncthreads();

        int idx = bid * THR + tid;          // float2 position over B*D: 0..8191
        const float* base = g_partial + (size_t)idx * 2;
        float ax = 0.f, ay = 0.f;
#pragma unroll 16
        for (int c = 0; c < SCHUNKS; c++) { // fixed ascending order
            float2 v = *(const float2*)(base + (size_t)c * (B * D));
            ax += v.x; ay += v.y;
        }
        const float inv = 1.0f / (float)S;
        *(float2*)(g_mean + (size_t)idx * 2) = make_float2(ax * inv, ay * inv);

        __syncthreads();
        if (tid == 0) {
            __threadfence();                // release mean writes
            atomicAdd(&g_c1, 1);
        }
        return;
    }

    // ---------------- Expert role ----------------
    int e    = bid - FOLD_BLOCKS;           // 0..63
    int lane = tid & 31;
    int bb   = tid >> 5;                    // warp = batch 0..7

    // Prefetch W[e] into smem — its DRAM read hides under remaining streaming
    {
        const float4* __restrict__ wp = (const float4*)(W + (size_t)e * D);
#pragma unroll
        for (int i = tid; i < D / 4; i += THR) wsm[i] = wp[i];
    }

    if (tid == 0) {
        while (*(volatile int*)&g_c1 != FOLD_BLOCKS) __nanosleep(64);  // park
        __threadfence();                    // acquire g_mean
    }
    __syncthreads();

    {
        const float4* __restrict__ xp = (const float4*)(g_mean + (size_t)bb * D);
        float sum = 0.f;
#pragma unroll
        for (int i = 0; i < (D / 4) / 32; i++) {   // 16 float4 per lane
            int idx   = lane + i * 32;
            float4 w4 = wsm[idx];
            float4 x4 = xp[idx];
            sum += w4.x * x4.x + w4.y * x4.y + w4.z * x4.z + w4.w * x4.w;
        }
#pragma unroll
        for (int o = 16; o > 0; o >>= 1) sum += __shfl_xor_sync(0xffffffffu, sum, o);
        if (lane == 0) g_logits[bb * E + e] = sum + bias[e];
    }
    __syncthreads();

    // ---------------- Final: ticket -> top-2 + softmax ----------------
    if (tid == 0) {
        __threadfence();                    // release this block's logits
        int tk = atomicAdd(&g_c2, 1);
        if (tk == EXPERT_BLOCKS - 1) __threadfence();  // acquire all logits
        s_ticket = tk;
    }
    __syncthreads();

    if (s_ticket == EXPERT_BLOCKS - 1) {
        for (int i = tid; i < B * E; i += THR) s_logits[i] = g_logits[i];
        __syncthreads();

        if (tid < B) {
            const float* lg = s_logits + tid * E;
            float v1 = -1e30f, v2 = -1e30f;
            int   i1 = 0, i2 = 0;
#pragma unroll
            for (int k = 0; k < E; k++) {
                float v = lg[k];
                if (v > v1) { v2 = v1; i2 = i1; v1 = v; i1 = k; }
                else if (v > v2) { v2 = v; i2 = k; }
            }
            float e2 = __expf(v2 - v1);     // stable 2-way softmax
            float denom = 1.0f + e2;
            out[tid * 2 + 0]      = 1.0f / denom;
            out[tid * 2 + 1]      = e2 / denom;
            out[16 + tid * 2 + 0] = (float)i1;
            out[16 + tid * 2 + 1] = (float)i2;
        }
        __syncthreads();
        if (tid == 0) {                     // reset for next graph replay;
            __threadfence();                // every counter consumer has passed
            g_c0 = 0;
            g_c1 = 0;
            g_c2 = 0;
        }
    }
}

extern "C" void kernel_launch(void* const* d_in, const int* in_sizes, int n_in,
                              void* d_out, int out_size) {
    const float* x    = (const float*)d_in[0];  // [B, S, D] fp32
    const float* W    = (const float*)d_in[1];  // [E, D]   fp32
    const float* bias = (const float*)d_in[2];  // [E]      fp32
    float* out        = (float*)d_out;          // 32 floats: weights then indices

    fused_kernel<<<GRID, THR>>>(x, W, bias, out);
}